// round 3
// baseline (speedup 1.0000x reference)
#include <cuda_runtime.h>
#include <math.h>

// Shapes (fixed per reference setup_inputs)
#define BB    4
#define NRES  300
#define NCLS  80
#define NKPT  17
#define HMW   64
#define HMHW  4096
#define NWRD  10          // ceil(300/32) suppression-mask words per row

#define IOU_THRF   0.7f
#define SCORE_THRF 0.01f
#define NEGV       (-1000000000.0f)

// Output layout (float32, flattened tuple concat):
// fl [4,300] @0 | fb [4,300,4] @1200 | fs [4,300] @6000 |
// akpts [4,300,17,3] @7200 | vkeep [4,300] @68400   (total 69600)
#define OFF_FL 0
#define OFF_FB 1200
#define OFF_FS 6000
#define OFF_AK 7200
#define OFF_VK 68400

// Scratch (device globals — no allocation allowed)
__device__ int   g_sel[BB * NRES];
__device__ int   g_kv[BB * NRES];
__device__ float g_boxsel[BB * NRES * 4];

// ---------------------------------------------------------------------------
// Kernel A: per-batch scores/labels, abs boxes, stable sort, NMS, outputs
// ---------------------------------------------------------------------------
__global__ __launch_bounds__(512) void nms_kernel(
    const float* __restrict__ logits,   // [4,300,80]
    const float* __restrict__ boxes,    // [4,300,4] cxcywh
    const float* __restrict__ sizes,    // [4,2]
    float* __restrict__ out)
{
    const int b   = blockIdx.x;
    const int tid = threadIdx.x;

    __shared__ float sc[NRES];          // sigmoid score
    __shared__ int   lb[NRES];          // argmax label
    __shared__ float bx[NRES * 4];      // abs xyxy boxes (unsorted)
    __shared__ float sv[NRES];          // score or NEG (for sort)
    __shared__ int   vd[NRES];          // valid flag (unsorted)
    __shared__ int   order[NRES];       // sorted -> original index
    __shared__ float ob[NRES * 4];      // sorted, class-offset boxes
    __shared__ float area[NRES];        // areas from offset coords
    __shared__ int   vv[NRES];          // valid, sorted
    __shared__ unsigned mask[NRES * NWRD]; // suppression candidates (j>i)
    __shared__ int   keep[NRES];
    __shared__ int   ti[NRES];
    __shared__ float red[32];
    __shared__ float s_maxc;

    const float s0 = sizes[b * 2 + 0];
    const float s1 = sizes[b * 2 + 1];

    // ---- per-row: logits max/argmax (first occurrence), sigmoid, abs box ----
    if (tid < NRES) {
        const float* lrow = logits + ((size_t)b * NRES + tid) * NCLS;
        float mv = lrow[0]; int mi = 0;
        #pragma unroll 4
        for (int c = 1; c < NCLS; c++) {
            float v = lrow[c];
            if (v > mv) { mv = v; mi = c; }
        }
        float score = 1.0f / (1.0f + expf(-mv));
        sc[tid] = score;
        lb[tid] = mi;

        const float* brow = boxes + ((size_t)b * NRES + tid) * 4;
        float cx = brow[0], cy = brow[1], w = brow[2], h = brow[3];
        bx[tid * 4 + 0] = (cx - w * 0.5f) * s0;
        bx[tid * 4 + 1] = (cy - h * 0.5f) * s1;
        bx[tid * 4 + 2] = (cx + w * 0.5f) * s0;
        bx[tid * 4 + 3] = (cy + h * 0.5f) * s1;

        int valid = score > SCORE_THRF;
        vd[tid] = valid;
        sv[tid] = valid ? score : NEGV;
    }
    __syncthreads();

    // ---- maxc = max(|abs_boxes|) + 1 over the batch ----
    {
        float lmax = 0.0f;
        for (int i = tid; i < NRES * 4; i += blockDim.x)
            lmax = fmaxf(lmax, fabsf(bx[i]));
        #pragma unroll
        for (int o = 16; o; o >>= 1)
            lmax = fmaxf(lmax, __shfl_down_sync(0xffffffffu, lmax, o));
        if ((tid & 31) == 0) red[tid >> 5] = lmax;
        __syncthreads();
        if (tid < 32) {
            float v = (tid < (int)(blockDim.x >> 5)) ? red[tid] : 0.0f;
            #pragma unroll
            for (int o = 16; o; o >>= 1)
                v = fmaxf(v, __shfl_down_sync(0xffffffffu, v, o));
            if (tid == 0) s_maxc = v + 1.0f;
        }
        __syncthreads();
    }
    const float maxc = s_maxc;

    // ---- stable descending rank (replicates jnp.argsort(-s), stable) ----
    if (tid < NRES) {
        float si = sv[tid];
        int r = 0;
        for (int j = 0; j < NRES; j++) {
            float sj = sv[j];
            r += (sj > si) || (sj == si && j < tid);
        }
        order[r] = tid;
    }
    __syncthreads();

    // ---- sorted, class-offset boxes + areas (areas from offset coords!) ----
    if (tid < NRES) {
        int i = order[tid];
        vv[tid] = vd[i];
        float off = (float)lb[i] * maxc;
        float x1 = bx[i * 4 + 0] + off;
        float y1 = bx[i * 4 + 1] + off;
        float x2 = bx[i * 4 + 2] + off;
        float y2 = bx[i * 4 + 3] + off;
        ob[tid * 4 + 0] = x1;
        ob[tid * 4 + 1] = y1;
        ob[tid * 4 + 2] = x2;
        ob[tid * 4 + 3] = y2;
        area[tid] = (x2 - x1) * (y2 - y1);
    }
    __syncthreads();

    // ---- suppression candidate bitmask: mask[r][w] bit jj => iou(r, w*32+jj)>thr, j>r ----
    for (int task = tid; task < NRES * NWRD; task += blockDim.x) {
        int r = task / NWRD;
        int w = task % NWRD;
        float x1 = ob[r * 4 + 0], y1 = ob[r * 4 + 1];
        float x2 = ob[r * 4 + 2], y2 = ob[r * 4 + 3];
        float ar = area[r];
        unsigned m = 0;
        int j0 = w * 32;
        #pragma unroll 8
        for (int jj = 0; jj < 32; jj++) {
            int j = j0 + jj;
            if (j > r && j < NRES) {
                float iw = fminf(x2, ob[j * 4 + 2]) - fmaxf(x1, ob[j * 4 + 0]);
                iw = fmaxf(iw, 0.0f);
                float ih = fminf(y2, ob[j * 4 + 3]) - fmaxf(y1, ob[j * 4 + 1]);
                ih = fmaxf(ih, 0.0f);
                float inter = iw * ih;
                float iou = inter / (ar + area[j] - inter + 1e-9f);
                if (iou > IOU_THRF) m |= (1u << jj);
            }
        }
        mask[r * NWRD + w] = m;
    }
    __syncthreads();

    // ---- greedy pass: warp 0, lanes 0..9 each own one 32-bit suppression word ----
    if (tid < 32) {
        unsigned sw = 0;
        for (int i = 0; i < NRES; i++) {
            unsigned word = __shfl_sync(0xffffffffu, sw, i >> 5);
            int suppressed = (word >> (i & 31)) & 1;
            int is_keep = vv[i] & (suppressed ^ 1);
            if (tid == 0) keep[i] = is_keep;
            if (is_keep && tid < NWRD) sw |= mask[i * NWRD + tid];
        }
    }
    __syncthreads();

    // ---- ti: kept (sorted order) then suppressed (ascending) — this IS top_k(N) ----
    if (tid == 0) {
        int p = 0;
        for (int i = 0; i < NRES; i++) if (keep[i])  ti[p++] = i;
        for (int i = 0; i < NRES; i++) if (!keep[i]) ti[p++] = i;
    }
    __syncthreads();

    // ---- outputs + scratch for kernel B ----
    if (tid < NRES) {
        int t   = tid;
        int tt  = ti[t];
        int kv  = keep[tt];
        int sel = order[tt];
        int gi  = b * NRES + t;

        g_sel[gi] = sel;
        g_kv[gi]  = kv;

        float b0 = bx[sel * 4 + 0], b1 = bx[sel * 4 + 1];
        float b2 = bx[sel * 4 + 2], b3 = bx[sel * 4 + 3];
        g_boxsel[gi * 4 + 0] = b0;
        g_boxsel[gi * 4 + 1] = b1;
        g_boxsel[gi * 4 + 2] = b2;
        g_boxsel[gi * 4 + 3] = b3;

        out[OFF_FL + gi] = kv ? (float)lb[sel] : -1.0f;
        float* fb = out + OFF_FB + (size_t)gi * 4;
        fb[0] = kv ? b0 : 0.0f;
        fb[1] = kv ? b1 : 0.0f;
        fb[2] = kv ? b2 : 0.0f;
        fb[3] = kv ? b3 : 0.0f;
        out[OFF_FS + gi] = kv ? sc[sel] : 0.0f;
        out[OFF_VK + gi] = kv ? 1.0f : 0.0f;
    }
}

// ---------------------------------------------------------------------------
// Kernel B: heatmap max/argmax per (b, out-slot t, k) with fused gather by sel,
// writes akpts directly. DRAM-bound: reads the full 334 MB heatmap once.
// ---------------------------------------------------------------------------
__global__ __launch_bounds__(256) void kpt_kernel(
    const float* __restrict__ hm,     // [4,300,17,4096]
    const float* __restrict__ koff,   // [4,300,17,2]
    float* __restrict__ out)
{
    const int bid = blockIdx.x;           // b*300*17 + t*17 + k
    const int k  = bid % NKPT;
    const int bt = bid / NKPT;
    const int t  = bt % NRES;
    const int b  = bt / NRES;
    const int gi = b * NRES + t;

    const int sel = g_sel[gi];
    const float4* row4 =
        (const float4*)(hm + (((size_t)(b * NRES + sel)) * NKPT + k) * HMHW);

    const int tid = threadIdx.x;

    float best = -3.402823466e38f;
    int   bi   = 0x7fffffff;
    #pragma unroll
    for (int j = 0; j < 4; j++) {
        float4 v = row4[tid + j * 256];
        int base = (tid + j * 256) * 4;
        if (v.x > best) { best = v.x; bi = base;     }
        if (v.y > best) { best = v.y; bi = base + 1; }
        if (v.z > best) { best = v.z; bi = base + 2; }
        if (v.w > best) { best = v.w; bi = base + 3; }
    }
    // warp reduce, min-index tie-break
    #pragma unroll
    for (int o = 16; o; o >>= 1) {
        float ov = __shfl_down_sync(0xffffffffu, best, o);
        int   oi = __shfl_down_sync(0xffffffffu, bi, o);
        if (ov > best || (ov == best && oi < bi)) { best = ov; bi = oi; }
    }
    __shared__ float svv[8];
    __shared__ int   sii[8];
    if ((tid & 31) == 0) { svv[tid >> 5] = best; sii[tid >> 5] = bi; }
    __syncthreads();

    if (tid == 0) {
        #pragma unroll
        for (int w = 1; w < 8; w++) {
            if (svv[w] > best || (svv[w] == best && sii[w] < bi)) {
                best = svv[w]; bi = sii[w];
            }
        }
        const int   kv   = g_kv[gi];
        const float* ko  = koff + (((size_t)(b * NRES + sel)) * NKPT + k) * 2;
        float nx = __int2float_rn(bi % HMW) / (float)(HMW - 1) + ko[0];
        nx = fminf(fmaxf(nx, 0.0f), 1.0f);
        float ny = __int2float_rn(bi / HMW) / (float)(HMW - 1) + ko[1];
        ny = fminf(fmaxf(ny, 0.0f), 1.0f);

        const float* bb = g_boxsel + (size_t)gi * 4;
        float x1 = bb[0], y1 = bb[1], x2 = bb[2], y2 = bb[3];
        float ax = x1 + nx * (x2 - x1);
        float ay = y1 + ny * (y2 - y1);

        float* o = out + OFF_AK + ((size_t)gi * NKPT + k) * 3;
        o[0] = kv ? ax   : 0.0f;
        o[1] = kv ? ay   : 0.0f;
        o[2] = kv ? best : 0.0f;
    }
}

// ---------------------------------------------------------------------------
extern "C" void kernel_launch(void* const* d_in, const int* in_sizes, int n_in,
                              void* d_out, int out_size)
{
    const float* logits = (const float*)d_in[0];  // pred_logits
    const float* boxes  = (const float*)d_in[1];  // pred_boxes
    const float* hm     = (const float*)d_in[2];  // pred_keypoint_heatmaps
    const float* koff   = (const float*)d_in[3];  // pred_keypoint_offsets
    const float* sizes  = (const float*)d_in[4];  // orig_target_sizes
    float* out = (float*)d_out;

    nms_kernel<<<BB, 512>>>(logits, boxes, sizes, out);
    kpt_kernel<<<BB * NRES * NKPT, 256>>>(hm, koff, out);
}

// round 4
// speedup vs baseline: 1.3530x; 1.3530x over previous
#include <cuda_runtime.h>
#include <math.h>

// Shapes (fixed per reference setup_inputs)
#define BB    4
#define NRES  300
#define NCLS  80
#define NKPT  17
#define HMW   64
#define HMHW  4096
#define NWRD  10                     // ceil(300/32)
#define NROWS (BB * NRES * NKPT)     // 20400 heatmap rows

#define IOU_THRF   0.7f
#define SCORE_THRF 0.01f
#define NEGV       (-1000000000.0f)

// Output layout (float32, flattened tuple concat):
// fl [4,300] @0 | fb [4,300,4] @1200 | fs [4,300] @6000 |
// akpts [4,300,17,3] @7200 | vkeep [4,300] @68400
#define OFF_FL 0
#define OFF_FB 1200
#define OFF_FS 6000
#define OFF_AK 7200
#define OFF_VK 68400

// Scratch (device globals — no allocation allowed)
__device__ int   g_sel[BB * NRES];
__device__ int   g_kv[BB * NRES];
__device__ float g_boxsel[BB * NRES * 4];
__device__ float g_maxv[NROWS];
__device__ int   g_midx[NROWS];

// ---------------------------------------------------------------------------
// Merged kernel: blocks 0..3 = per-batch NMS (runs concurrently, hidden under
// the DRAM stream); blocks 4..20403 = heatmap max/argmax (ungathered).
// ---------------------------------------------------------------------------
__global__ __launch_bounds__(256) void main_kernel(
    const float* __restrict__ logits,   // [4,300,80]
    const float* __restrict__ boxes,    // [4,300,4] cxcywh
    const float* __restrict__ sizes,    // [4,2]
    const float* __restrict__ hm,       // [4,300,17,4096]
    float* __restrict__ out)
{
    const int tid = threadIdx.x;

    // ---- NMS shared state (allocated kernel-wide; ~32 KB) ----
    __shared__ float sc[NRES];
    __shared__ int   lb[NRES];
    __shared__ float bx[NRES * 4];
    __shared__ float sv[NRES];
    __shared__ int   order_[NRES];
    __shared__ float ob[NRES * 4];
    __shared__ float area[NRES];
    __shared__ int   vv[NRES];
    __shared__ unsigned mask[NRES * NWRD];
    __shared__ int   keep[NRES];
    __shared__ int   ti[NRES];
    __shared__ unsigned kw[NWRD];
    __shared__ float red[8];
    __shared__ float s_maxc;
    // ---- heatmap shared state ----
    __shared__ float wmax[8];
    __shared__ float sM;
    __shared__ int   sIdx;

    if (blockIdx.x >= BB) {
        // =============== heatmap max/argmax for one (b,n,k) row ===========
        const int row = blockIdx.x - BB;
        const float4* r4 = (const float4*)hm + (size_t)row * (HMHW / 4);

        // load 16 floats (4 coalesced float4 per thread) into registers
        float4 A = r4[tid];
        float4 Bv = r4[tid + 256];
        float4 Cv = r4[tid + 512];
        float4 Dv = r4[tid + 768];

        // pure fmaxf tree: thread max (no index tracking in the hot path)
        float tm = fmaxf(
            fmaxf(fmaxf(fmaxf(A.x, A.y), fmaxf(A.z, A.w)),
                  fmaxf(fmaxf(Bv.x, Bv.y), fmaxf(Bv.z, Bv.w))),
            fmaxf(fmaxf(fmaxf(Cv.x, Cv.y), fmaxf(Cv.z, Cv.w)),
                  fmaxf(fmaxf(Dv.x, Dv.y), fmaxf(Dv.z, Dv.w))));

        // block max (value only)
        float wm = tm;
        #pragma unroll
        for (int o = 16; o; o >>= 1)
            wm = fmaxf(wm, __shfl_xor_sync(0xffffffffu, wm, o));
        if ((tid & 31) == 0) wmax[tid >> 5] = wm;
        if (tid == 0) sIdx = 0x7fffffff;
        __syncthreads();
        if (tid == 0) {
            float M = wmax[0];
            #pragma unroll
            for (int w = 1; w < 8; w++) M = fmaxf(M, wmax[w]);
            sM = M;
        }
        __syncthreads();
        const float M = sM;

        // only matching thread(s) resolve first-occurrence global index
        if (tm == M) {
            float vals[16] = {A.x, A.y, A.z, A.w, Bv.x, Bv.y, Bv.z, Bv.w,
                              Cv.x, Cv.y, Cv.z, Cv.w, Dv.x, Dv.y, Dv.z, Dv.w};
            int gidx = 0x7fffffff;
            #pragma unroll
            for (int j = 0; j < 16; j++) {
                if (gidx == 0x7fffffff && vals[j] == M)
                    gidx = 4 * (tid + 256 * (j >> 2)) + (j & 3);
            }
            atomicMin(&sIdx, gidx);
        }
        __syncthreads();
        if (tid == 0) { g_maxv[row] = M; g_midx[row] = sIdx; }
        return;
    }

    // ======================= NMS for batch b ==============================
    const int b = blockIdx.x;
    const float s0 = sizes[b * 2 + 0];
    const float s1 = sizes[b * 2 + 1];

    // per-row: logits max/argmax (first occurrence), sigmoid, abs box
    for (int r = tid; r < NRES; r += 256) {
        const float* lrow = logits + ((size_t)b * NRES + r) * NCLS;
        float mv = lrow[0]; int mi = 0;
        #pragma unroll 4
        for (int c = 1; c < NCLS; c++) {
            float v = lrow[c];
            if (v > mv) { mv = v; mi = c; }
        }
        float score = 1.0f / (1.0f + expf(-mv));
        sc[r] = score;
        lb[r] = mi;

        const float* brow = boxes + ((size_t)b * NRES + r) * 4;
        float cx = brow[0], cy = brow[1], w = brow[2], h = brow[3];
        bx[r * 4 + 0] = (cx - w * 0.5f) * s0;
        bx[r * 4 + 1] = (cy - h * 0.5f) * s1;
        bx[r * 4 + 2] = (cx + w * 0.5f) * s0;
        bx[r * 4 + 3] = (cy + h * 0.5f) * s1;
        sv[r] = (score > SCORE_THRF) ? score : NEGV;
    }
    __syncthreads();

    // maxc = max(|abs_boxes|) + 1
    {
        float lmax = 0.0f;
        for (int i = tid; i < NRES * 4; i += 256)
            lmax = fmaxf(lmax, fabsf(bx[i]));
        #pragma unroll
        for (int o = 16; o; o >>= 1)
            lmax = fmaxf(lmax, __shfl_down_sync(0xffffffffu, lmax, o));
        if ((tid & 31) == 0) red[tid >> 5] = lmax;
        __syncthreads();
        if (tid == 0) {
            float v = red[0];
            #pragma unroll
            for (int w = 1; w < 8; w++) v = fmaxf(v, red[w]);
            s_maxc = v + 1.0f;
        }
        __syncthreads();
    }
    const float maxc = s_maxc;

    // stable descending rank (replicates stable argsort(-s))
    for (int r = tid; r < NRES; r += 256) {
        float si = sv[r];
        int rk = 0;
        for (int j = 0; j < NRES; j++) {
            float sj = sv[j];
            rk += (sj > si) || (sj == si && j < r);
        }
        order_[rk] = r;
    }
    __syncthreads();

    // sorted, class-offset boxes + areas (areas from offset coords)
    for (int t = tid; t < NRES; t += 256) {
        int i = order_[t];
        vv[t] = sv[i] != NEGV;
        float off = (float)lb[i] * maxc;
        float x1 = bx[i * 4 + 0] + off;
        float y1 = bx[i * 4 + 1] + off;
        float x2 = bx[i * 4 + 2] + off;
        float y2 = bx[i * 4 + 3] + off;
        ob[t * 4 + 0] = x1;
        ob[t * 4 + 1] = y1;
        ob[t * 4 + 2] = x2;
        ob[t * 4 + 3] = y2;
        area[t] = (x2 - x1) * (y2 - y1);
    }
    __syncthreads();

    // suppression bitmask: mask[r][w] bit jj => iou(r, w*32+jj)>thr, j>r
    // task mapping keeps r consecutive / w uniform within a warp (broadcast LDS)
    for (int task = tid; task < NRES * NWRD; task += 256) {
        int r = task % NRES;
        int w = task / NRES;
        float x1 = ob[r * 4 + 0], y1 = ob[r * 4 + 1];
        float x2 = ob[r * 4 + 2], y2 = ob[r * 4 + 3];
        float ar = area[r];
        unsigned m = 0;
        int j0 = w * 32;
        #pragma unroll 8
        for (int jj = 0; jj < 32; jj++) {
            int j = j0 + jj;
            if (j > r && j < NRES) {
                float iw = fmaxf(fminf(x2, ob[j * 4 + 2]) - fmaxf(x1, ob[j * 4 + 0]), 0.0f);
                float ih = fmaxf(fminf(y2, ob[j * 4 + 3]) - fmaxf(y1, ob[j * 4 + 1]), 0.0f);
                float inter = iw * ih;
                float iou = inter / (ar + area[j] - inter + 1e-9f);
                if (iou > IOU_THRF) m |= (1u << jj);
            }
        }
        mask[r * NWRD + w] = m;
    }
    __syncthreads();

    // greedy pass: warp 0, lanes 0..9 each own one 32-bit suppression word
    if (tid < 32) {
        unsigned sw = 0;
        for (int i = 0; i < NRES; i++) {
            unsigned word = __shfl_sync(0xffffffffu, sw, i >> 5);
            int suppressed = (word >> (i & 31)) & 1;
            int is_keep = vv[i] & (suppressed ^ 1);
            if (tid == 0) keep[i] = is_keep;
            if (is_keep && tid < NWRD) sw |= mask[i * NWRD + tid];
        }
    }
    __syncthreads();

    // pack keep bitmask words
    if (tid < NWRD) {
        unsigned m = 0;
        for (int jj = 0; jj < 32; jj++) {
            int i = tid * 32 + jj;
            if (i < NRES && keep[i]) m |= (1u << jj);
        }
        kw[tid] = m;
    }
    __syncthreads();

    // ti: kept (sorted order) then suppressed (ascending) — parallel prefix
    for (int t = tid; t < NRES; t += 256) {
        int wt = t >> 5, bt_ = t & 31;
        int cnt = 0, K = 0;
        #pragma unroll
        for (int w = 0; w < NWRD; w++) {
            int pc = __popc(kw[w]);
            K += pc;
            if (w < wt) cnt += pc;
        }
        cnt += __popc(kw[wt] & ((1u << bt_) - 1u));
        int p = keep[t] ? cnt : (K + t - cnt);
        ti[p] = t;
    }
    __syncthreads();

    // outputs + scratch for finalize
    for (int t = tid; t < NRES; t += 256) {
        int tt  = ti[t];
        int kv  = keep[tt];
        int sel = order_[tt];
        int gi  = b * NRES + t;

        g_sel[gi] = sel;
        g_kv[gi]  = kv;

        float b0 = bx[sel * 4 + 0], b1 = bx[sel * 4 + 1];
        float b2 = bx[sel * 4 + 2], b3 = bx[sel * 4 + 3];
        g_boxsel[gi * 4 + 0] = b0;
        g_boxsel[gi * 4 + 1] = b1;
        g_boxsel[gi * 4 + 2] = b2;
        g_boxsel[gi * 4 + 3] = b3;

        out[OFF_FL + gi] = kv ? (float)lb[sel] : -1.0f;
        float* fb = out + OFF_FB + (size_t)gi * 4;
        fb[0] = kv ? b0 : 0.0f;
        fb[1] = kv ? b1 : 0.0f;
        fb[2] = kv ? b2 : 0.0f;
        fb[3] = kv ? b3 : 0.0f;
        out[OFF_FS + gi] = kv ? sc[sel] : 0.0f;
        out[OFF_VK + gi] = kv ? 1.0f : 0.0f;
    }
}

// ---------------------------------------------------------------------------
// Finalize: gather (maxv, idx) by sel, compute akpts. One thread per output.
// ---------------------------------------------------------------------------
__global__ __launch_bounds__(256) void finalize_kernel(
    const float* __restrict__ koff,   // [4,300,17,2]
    float* __restrict__ out)
{
    int i = blockIdx.x * 256 + threadIdx.x;   // (b, t, k) flattened
    if (i >= NROWS) return;
    int k  = i % NKPT;
    int gi = i / NKPT;
    int b  = gi / NRES;

    int sel = g_sel[gi];
    int kv  = g_kv[gi];
    int row = (b * NRES + sel) * NKPT + k;

    float mv = g_maxv[row];
    int   bi = g_midx[row];
    const float* ko = koff + (size_t)row * 2;

    float nx = fminf(fmaxf(__int2float_rn(bi % HMW) / (float)(HMW - 1) + ko[0], 0.0f), 1.0f);
    float ny = fminf(fmaxf(__int2float_rn(bi / HMW) / (float)(HMW - 1) + ko[1], 0.0f), 1.0f);

    float x1 = g_boxsel[gi * 4 + 0], y1 = g_boxsel[gi * 4 + 1];
    float x2 = g_boxsel[gi * 4 + 2], y2 = g_boxsel[gi * 4 + 3];
    float ax = x1 + nx * (x2 - x1);
    float ay = y1 + ny * (y2 - y1);

    float* o = out + OFF_AK + (size_t)i * 3;
    o[0] = kv ? ax : 0.0f;
    o[1] = kv ? ay : 0.0f;
    o[2] = kv ? mv : 0.0f;
}

// ---------------------------------------------------------------------------
extern "C" void kernel_launch(void* const* d_in, const int* in_sizes, int n_in,
                              void* d_out, int out_size)
{
    const float* logits = (const float*)d_in[0];  // pred_logits
    const float* boxes  = (const float*)d_in[1];  // pred_boxes
    const float* hm     = (const float*)d_in[2];  // pred_keypoint_heatmaps
    const float* koff   = (const float*)d_in[3];  // pred_keypoint_offsets
    const float* sizes  = (const float*)d_in[4];  // orig_target_sizes
    float* out = (float*)d_out;

    main_kernel<<<BB + NROWS, 256>>>(logits, boxes, sizes, hm, out);
    finalize_kernel<<<(NROWS + 255) / 256, 256>>>(koff, out);
}